// round 9
// baseline (speedup 1.0000x reference)
#include <cuda_runtime.h>
#include <cuda_fp16.h>
#include <cstdint>

// ---------------- problem constants ----------------
#define KTOT 4096
#define NTOT 11008
#define MTOT 8192
#define KB2  2048            // packed bytes per W row (KTOT/2)

#define MT 128
#define NT 128
#define BK 64
#define STAGES 4
#define THREADS 256
#define CHUNKS (KTOT / BK)          // 64

#define A_BYTES (MT * BK * 2)            // 16384
#define B_BYTES (NT * (BK / 2))          // 4096 packed int4
#define STAGE_BYTES (A_BYTES + B_BYTES)  // 20480
#define SMEM_TOTAL (STAGES * STAGE_BYTES) // 81920 -> 2 CTAs/SM (160KB)

// ---------------- scratch (device globals, no allocs) ----------------
__device__ __align__(16) __half   g_Xh[(size_t)MTOT * KTOT];   // 67 MB fp16 x
__device__ __align__(16) uint8_t  g_Wq[(size_t)NTOT * KB2];    // 22.5 MB packed int4

// ---------------- helpers ----------------
__device__ __forceinline__ uint32_t smem_u32(const void* p) {
    uint32_t a;
    asm("{ .reg .u64 t; cvta.to.shared.u64 t, %1; cvt.u32.u64 %0, t; }"
        : "=r"(a) : "l"(p));
    return a;
}
// A tile: 128-byte rows (64 fp16), XOR swizzle conflict-free for ldmatrix + cp.async
__device__ __forceinline__ uint32_t swz(int row, int g) {
    return (uint32_t)((row << 7) + (((g ^ (row & 7)) & 7) << 4));
}
__device__ __forceinline__ void cp16(uint32_t dst, const void* src) {
    asm volatile("cp.async.cg.shared.global [%0], [%1], 16;"
                 :: "r"(dst), "l"(src) : "memory");
}
__device__ __forceinline__ void cp_commit() {
    asm volatile("cp.async.commit_group;" ::: "memory");
}
__device__ __forceinline__ void cp_wait1() {
    asm volatile("cp.async.wait_group 1;" ::: "memory");
}
__device__ __forceinline__ void cp_wait2() {
    asm volatile("cp.async.wait_group 2;" ::: "memory");
}
__device__ __forceinline__ void ldsm4(uint32_t* r, uint32_t addr) {
    asm volatile("ldmatrix.sync.aligned.m8n8.x4.shared.b16 {%0,%1,%2,%3}, [%4];"
                 : "=r"(r[0]), "=r"(r[1]), "=r"(r[2]), "=r"(r[3]) : "r"(addr));
}
__device__ __forceinline__ void mma16816(float* c, const uint32_t* a,
                                         uint32_t b0, uint32_t b1) {
    asm volatile(
        "mma.sync.aligned.m16n8k16.row.col.f32.f16.f16.f32 "
        "{%0,%1,%2,%3}, {%4,%5,%6,%7}, {%8,%9}, {%0,%1,%2,%3};"
        : "+f"(c[0]), "+f"(c[1]), "+f"(c[2]), "+f"(c[3])
        : "r"(a[0]), "r"(a[1]), "r"(a[2]), "r"(a[3]), "r"(b0), "r"(b1));
}
// int4 pair dequant: byte j of u0 -> b0 (k even/odd pair), byte j of u1 -> b1 (k+8)
// magic: ((nib ^ 8) | 0x6400) as fp16 = 1032 + w  ->  subtract 1032 (exact)
// every shifted term masked independently (prmt leaves garbage in t[2..3])
__device__ __forceinline__ void deq(uint32_t u0, uint32_t u1, uint32_t sel,
                                    uint32_t& b0, uint32_t& b1) {
    uint32_t t;
    asm("prmt.b32 %0, %1, %2, %3;" : "=r"(t) : "r"(u0), "r"(u1), "r"(sel));
    uint32_t v0 = (t & 0x0000000Fu)         | ((t << 12) & 0x000F0000u);
    uint32_t v1 = ((t >> 8) & 0x0000000Fu)  | ((t << 4)  & 0x000F0000u);
    v0 = (v0 ^ 0x00080008u) | 0x64006400u;
    v1 = (v1 ^ 0x00080008u) | 0x64006400u;
    const uint32_t kc = 0x64086408u;                      // half2(1032,1032)
    __half2 h0 = __hsub2(*reinterpret_cast<__half2*>(&v0),
                         *reinterpret_cast<const __half2*>(&kc));
    __half2 h1 = __hsub2(*reinterpret_cast<__half2*>(&v1),
                         *reinterpret_cast<const __half2*>(&kc));
    b0 = *reinterpret_cast<uint32_t*>(&h0);
    b1 = *reinterpret_cast<uint32_t*>(&h1);
}

// ---------------- fused prep kernel ----------------
#define MK4 ((size_t)(MTOT / 4) * KTOT)              // 8,388,608 (x convert, float4)
#define WPK ((size_t)NTOT * KB2 / 4)                 // 5,636,096 (W pack, 4B each)
__global__ void prep_kernel(const int4* __restrict__ q, const float4* __restrict__ x) {
    size_t i = (size_t)blockIdx.x * THREADS + threadIdx.x;
    if (i < WPK) {
        int4 qv = q[i];   // 4 int32, each one packed byte (2 nibbles)
        uint32_t p = (qv.x & 0xFF) | ((qv.y & 0xFF) << 8) |
                     ((qv.z & 0xFF) << 16) | ((uint32_t)qv.w << 24);
        reinterpret_cast<uint32_t*>(g_Wq)[i] = p;
    }
    float4 xv = x[i];
    __half2* o = reinterpret_cast<__half2*>(g_Xh);
    o[2 * i]     = __floats2half2_rn(xv.x, xv.y);
    o[2 * i + 1] = __floats2half2_rn(xv.z, xv.w);
}

// ---------------- GEMM ----------------
__device__ __forceinline__ void load_chunk(int c, int stage, uint32_t sb,
                                           const __half* Ag, const uint8_t* Bq,
                                           int tid) {
    uint32_t s_a = sb + stage * STAGE_BYTES;
    uint32_t s_b = s_a + A_BYTES;
    const char* a = reinterpret_cast<const char*>(Ag) + (size_t)c * BK * 2;
#pragma unroll
    for (int i = 0; i < 4; i++) {            // A: 128 rows x 8 x 16B
        int v = tid + i * THREADS;
        int row = v >> 3, g = v & 7;
        cp16(s_a + swz(row, g), a + (size_t)row * (KTOT * 2) + g * 16);
    }
    {                                        // B: 128 rows x 32B packed
        int row = tid >> 1, h = tid & 1;
        cp16(s_b + row * 32 + h * 16,
             Bq + (size_t)row * KB2 + c * 32 + h * 16);
    }
}

__device__ __forceinline__ void load_afrag(uint32_t sa, int kk, int wm, int lane,
                                           uint32_t af[4][4]) {
    int gg = kk * 2 + (lane >> 4);
#pragma unroll
    for (int mt = 0; mt < 4; mt++) {
        int row = wm + mt * 16 + (lane & 15);
        ldsm4(af[mt], sa + swz(row, gg));
    }
}

__device__ __forceinline__ void load_u(uint32_t s_b, int kk, int lane, int wn,
                                       uint2 u[4]) {
#pragma unroll
    for (int nt = 0; nt < 4; nt++) {
        int row = wn + nt * 8 + (lane >> 2);
        uint32_t addr = s_b + row * 32 + kk * 8;
        asm volatile("ld.shared.v2.u32 {%0, %1}, [%2];"
                     : "=r"(u[nt].x), "=r"(u[nt].y) : "r"(addr));
    }
}

__global__ void __launch_bounds__(THREADS, 2)
gemm_kernel(const float* __restrict__ scales, const float* __restrict__ bias,
            float* __restrict__ out) {
    extern __shared__ char smem[];
    uint32_t sb = smem_u32(smem);
    int tid = threadIdx.x, lane = tid & 31, wid = tid >> 5;

    // grouped rasterization (8 m-tiles per group) for L2 reuse of the W panel
    const int NTILES = NTOT / NT;   // 86
    const int GROUP = 8;
    int pid = blockIdx.x;
    int gsz = GROUP * NTILES;
    int g = pid / gsz, r = pid % gsz;
    int mtile = g * GROUP + (r % GROUP);
    int ntile = r / GROUP;
    int m0 = mtile * MT, n0 = ntile * NT;

    const __half*  Ag = g_Xh + (size_t)m0 * KTOT;
    const uint8_t* Bq = g_Wq + (size_t)n0 * KB2;

    // warp grid: 2 (m) x 4 (n); warp tile 64x32
    const int wm = (wid >> 2) * 64;
    const int wn = (wid & 3) * 32;
    const uint32_t sel = 17u * (lane & 3) + 64u;   // PRMT: byte0=u0.j, byte1=u1.j

    float acc[4][4][4];
#pragma unroll
    for (int i = 0; i < 4; i++)
#pragma unroll
        for (int j = 0; j < 4; j++)
#pragma unroll
            for (int l = 0; l < 4; l++) acc[i][j][l] = 0.0f;

    // prologue: 3 stages in flight
#pragma unroll
    for (int s = 0; s < STAGES - 1; s++) {
        load_chunk(s, s, sb, Ag, Bq, tid);
        cp_commit();
    }
    // chunk 0 resident -> preload step-0 fragments
    cp_wait2();
    __syncthreads();
    uint32_t af[2][4][4];
    uint2 u[4];
    load_afrag(sb, 0, wm, lane, af[0]);
    load_u(sb + A_BYTES, 0, lane, wn, u);

    int stage = 0;
    for (int c = 0; c < CHUNKS; c++) {
        cp_wait1();              // chunks c AND c+1 resident
        __syncthreads();         // all warps done reading the stage we overwrite

        uint32_t sa  = sb + stage * STAGE_BYTES;
        uint32_t s_b = sa + A_BYTES;
        int snext = stage + 1; if (snext == STAGES) snext = 0;
        uint32_t sa_n  = sb + snext * STAGE_BYTES;
        uint32_t s_b_n = sa_n + A_BYTES;

#pragma unroll
        for (int kk = 0; kk < 4; kk++) {
            int cur = kk & 1;
            // dequant current step's B (u) before it is overwritten
            uint32_t bq[4][2];
#pragma unroll
            for (int nt = 0; nt < 4; nt++)
                deq(u[nt].x, u[nt].y, sel, bq[nt][0], bq[nt][1]);
            // prefetch next step's fragments (step kk+1, or step 0 of chunk c+1)
            if (kk < 3) {
                load_afrag(sa, kk + 1, wm, lane, af[cur ^ 1]);
                load_u(s_b, kk + 1, lane, wn, u);
            } else {
                load_afrag(sa_n, 0, wm, lane, af[cur ^ 1]);
                load_u(s_b_n, 0, lane, wn, u);
            }
            // MMAs for this step
#pragma unroll
            for (int mt = 0; mt < 4; mt++)
#pragma unroll
                for (int nt = 0; nt < 4; nt++)
                    mma16816(acc[mt][nt], af[cur][mt], bq[nt][0], bq[nt][1]);
            // gmem refill issued after step-0 MMAs so barrier->MMA path stays hot
            if (kk == 0) {
                int cn = c + STAGES - 1;
                if (cn < CHUNKS) {
                    int st = stage + STAGES - 1; if (st >= STAGES) st -= STAGES;
                    load_chunk(cn, st, sb, Ag, Bq, tid);
                }
                cp_commit();     // keep group count fixed at tail
            }
        }
        stage = snext;
    }

    // epilogue: scale (row-wise over N) + bias, fp32 stores
#pragma unroll
    for (int mt = 0; mt < 4; mt++) {
        int r0 = m0 + wm + mt * 16 + (lane >> 2);
        float* o0 = out + (size_t)r0 * NTOT;
        float* o1 = out + (size_t)(r0 + 8) * NTOT;
#pragma unroll
        for (int nt = 0; nt < 4; nt++) {
            int col = n0 + wn + nt * 8 + (lane & 3) * 2;
            float s0 = __ldg(scales + col), s1 = __ldg(scales + col + 1);
            float b0 = __ldg(bias + col),   b1 = __ldg(bias + col + 1);
            float2 v0, v1;
            v0.x = fmaf(acc[mt][nt][0], s0, b0);
            v0.y = fmaf(acc[mt][nt][1], s1, b1);
            v1.x = fmaf(acc[mt][nt][2], s0, b0);
            v1.y = fmaf(acc[mt][nt][3], s1, b1);
            *reinterpret_cast<float2*>(o0 + col) = v0;
            *reinterpret_cast<float2*>(o1 + col) = v1;
        }
    }
}

// ---------------- launch ----------------
extern "C" void kernel_launch(void* const* d_in, const int* in_sizes, int n_in,
                              void* d_out, int out_size) {
    const float* x      = (const float*)d_in[0];
    const int*   q      = (const int*)d_in[1];
    const float* scales = (const float*)d_in[2];
    const float* bias   = (const float*)d_in[3];
    float* out = (float*)d_out;

    prep_kernel<<<(int)(MK4 / THREADS), THREADS>>>((const int4*)q, (const float4*)x);

    cudaFuncSetAttribute(gemm_kernel, cudaFuncAttributeMaxDynamicSharedMemorySize,
                         SMEM_TOTAL);
    gemm_kernel<<<(MTOT / MT) * (NTOT / NT), THREADS, SMEM_TOTAL>>>(scales, bias, out);
}

// round 10
// speedup vs baseline: 1.0341x; 1.0341x over previous
#include <cuda_runtime.h>
#include <cuda_fp16.h>
#include <cstdint>

// ---------------- problem constants ----------------
#define KTOT 4096
#define NTOT 11008
#define MTOT 8192

#define MT 128
#define NT 128
#define BK 64
#define STAGES 3
#define THREADS 256
#define CHUNKS (KTOT / BK)          // 64

#define A_BYTES (MT * BK * 2)       // 16384
#define B_BYTES (NT * BK * 2)       // 16384
#define STAGE_BYTES (A_BYTES + B_BYTES)   // 32768
#define SMEM_TOTAL (STAGES * STAGE_BYTES) // 98304 (96KB) -> 2 CTAs/SM

// ---------------- scratch (device globals, no allocs) ----------------
__device__ __align__(16) __half g_Xh[(size_t)MTOT * KTOT];   // 67 MB
__device__ __align__(16) __half g_Wh[(size_t)NTOT * KTOT];   // 90 MB

// ---------------- helpers ----------------
__device__ __forceinline__ uint32_t smem_u32(const void* p) {
    uint32_t a;
    asm("{ .reg .u64 t; cvta.to.shared.u64 t, %1; cvt.u32.u64 %0, t; }"
        : "=r"(a) : "l"(p));
    return a;
}
// 128-byte rows (64 fp16), 8 16B groups/row, XOR by (row&7):
// conflict-free for ldmatrix 8-row phases AND cp.async writes.
__device__ __forceinline__ uint32_t swz(int row, int g) {
    return (uint32_t)((row << 7) + (((g ^ (row & 7)) & 7) << 4));
}
__device__ __forceinline__ void cp16(uint32_t dst, const void* src) {
    asm volatile("cp.async.cg.shared.global [%0], [%1], 16;"
                 :: "r"(dst), "l"(src) : "memory");
}
__device__ __forceinline__ void cp_commit() {
    asm volatile("cp.async.commit_group;" ::: "memory");
}
__device__ __forceinline__ void cp_wait0() {
    asm volatile("cp.async.wait_group 0;" ::: "memory");
}
__device__ __forceinline__ void ldsm4(uint32_t* r, uint32_t addr) {
    asm volatile("ldmatrix.sync.aligned.m8n8.x4.shared.b16 {%0,%1,%2,%3}, [%4];"
                 : "=r"(r[0]), "=r"(r[1]), "=r"(r[2]), "=r"(r[3]) : "r"(addr));
}
__device__ __forceinline__ void mma16816(float* c, const uint32_t* a,
                                         uint32_t b0, uint32_t b1) {
    asm volatile(
        "mma.sync.aligned.m16n8k16.row.col.f32.f16.f16.f32 "
        "{%0,%1,%2,%3}, {%4,%5,%6,%7}, {%8,%9}, {%0,%1,%2,%3};"
        : "+f"(c[0]), "+f"(c[1]), "+f"(c[2]), "+f"(c[3])
        : "r"(a[0]), "r"(a[1]), "r"(a[2]), "r"(a[3]), "r"(b0), "r"(b1));
}

// ---------------- fused prep kernel ----------------
#define NK2 (NTOT * (KTOT / 2))          // 22,544,384
#define MK4 ((MTOT / 4) * KTOT)          // 8,388,608
__global__ void prep_kernel(const int* __restrict__ q, const float4* __restrict__ x) {
    size_t i = (size_t)blockIdx.x * THREADS + threadIdx.x;
    int v = q[i];
    int lo = (((v & 15) + 8) & 15) - 8;
    int hi = ((((v >> 4) & 15) + 8) & 15) - 8;
    __half2 w;
    w.x = __int2half_rn(lo);
    w.y = __int2half_rn(hi);
    reinterpret_cast<__half2*>(g_Wh)[i] = w;
    if (i < (size_t)MK4) {
        float4 xv = x[i];
        __half2* o = reinterpret_cast<__half2*>(g_Xh);
        o[2 * i]     = __floats2half2_rn(xv.x, xv.y);
        o[2 * i + 1] = __floats2half2_rn(xv.z, xv.w);
    }
}

// ---------------- GEMM ----------------
__device__ __forceinline__ void load_chunk(int c, int stage, uint32_t sb,
                                           const __half* Ag, const __half* Bg,
                                           int tid) {
    uint32_t s_a = sb + stage * STAGE_BYTES;
    uint32_t s_b = s_a + A_BYTES;
    const char* a = reinterpret_cast<const char*>(Ag) + (size_t)c * BK * 2;
    const char* b = reinterpret_cast<const char*>(Bg) + (size_t)c * BK * 2;
    const size_t rowb = (size_t)KTOT * 2;
#pragma unroll
    for (int i = 0; i < 4; i++) {            // A: 128 rows x 8 vecs
        int v = tid + i * THREADS;
        int row = v >> 3, g = v & 7;
        cp16(s_a + swz(row, g), a + (size_t)row * rowb + g * 16);
    }
#pragma unroll
    for (int i = 0; i < 4; i++) {            // B: 128 rows x 8 vecs
        int v = tid + i * THREADS;
        int row = v >> 3, g = v & 7;
        cp16(s_b + swz(row, g), b + (size_t)row * rowb + g * 16);
    }
}

__device__ __forceinline__ void load_frags(uint32_t sa, uint32_t sB, int kk,
                                           int wm, int wn, int lane,
                                           uint32_t af[4][4], uint32_t bf[2][4]) {
    int gg = kk * 2 + (lane >> 4);
#pragma unroll
    for (int mt = 0; mt < 4; mt++) {
        int row = wm + mt * 16 + (lane & 15);
        ldsm4(af[mt], sa + swz(row, gg));
    }
#pragma unroll
    for (int np = 0; np < 2; np++) {
        int row = wn + np * 16 + (lane & 15);
        ldsm4(bf[np], sB + swz(row, gg));
    }
}

__global__ void __launch_bounds__(THREADS, 2)
gemm_kernel(const float* __restrict__ scales, const float* __restrict__ bias,
            float* __restrict__ out) {
    extern __shared__ char smem[];
    uint32_t sb = smem_u32(smem);
    int tid = threadIdx.x, lane = tid & 31, wid = tid >> 5;

    // grouped rasterization (8 m-tiles per group) for L2 reuse of the W panel
    const int NTILES = NTOT / NT;   // 86
    const int GROUP = 8;
    int pid = blockIdx.x;
    int gsz = GROUP * NTILES;
    int g = pid / gsz, r = pid % gsz;
    int mtile = g * GROUP + (r % GROUP);
    int ntile = r / GROUP;
    int m0 = mtile * MT, n0 = ntile * NT;

    const __half* Ag = g_Xh + (size_t)m0 * KTOT;
    const __half* Bg = g_Wh + (size_t)n0 * KTOT;

    // warp grid: 2 (m) x 4 (n); warp tile 64x32
    const int wm = (wid >> 2) * 64;
    const int wn = (wid & 3) * 32;

    float acc[4][4][4];
#pragma unroll
    for (int i = 0; i < 4; i++)
#pragma unroll
        for (int j = 0; j < 4; j++)
#pragma unroll
            for (int l = 0; l < 4; l++) acc[i][j][l] = 0.0f;

    // prologue: chunks 0 and 1 in flight, then publish and preload frags
    load_chunk(0, 0, sb, Ag, Bg, tid);
    cp_commit();
    load_chunk(1, 1, sb, Ag, Bg, tid);
    cp_commit();
    cp_wait0();
    __syncthreads();

    uint32_t af[2][4][4], bf[2][2][4];
    load_frags(sb, sb + A_BYTES, 0, wm, wn, lane, af[0], bf[0]);

    int stage = 0;
    for (int c = 0; c < CHUNKS; c++) {
        // invariant here: chunks c and c+1 resident+published;
        // step-0 frags of chunk c already in af[0]/bf[0]
        uint32_t sa  = sb + stage * STAGE_BYTES;
        uint32_t sB  = sa + A_BYTES;
        int snext = stage + 1; if (snext == STAGES) snext = 0;
        uint32_t sa_n = sb + snext * STAGE_BYTES;

#pragma unroll
        for (int kk = 0; kk < 4; kk++) {     // 4 k16 steps per BK=64 chunk
            int cur = kk & 1;
            if (kk < 3) {
                load_frags(sa, sB, kk + 1, wm, wn, lane, af[cur ^ 1], bf[cur ^ 1]);
            } else if (c + 1 < CHUNKS) {
                // cross-chunk prefetch: step 0 of chunk c+1 (resident by invariant)
                load_frags(sa_n, sa_n + A_BYTES, 0, wm, wn, lane,
                           af[cur ^ 1], bf[cur ^ 1]);
            }
#pragma unroll
            for (int mt = 0; mt < 4; mt++)
#pragma unroll
                for (int nt = 0; nt < 4; nt++)
                    mma16816(acc[mt][nt], af[cur][mt],
                             bf[cur][nt >> 1][nt & 1],
                             bf[cur][nt >> 1][(nt & 1) + 2]);
            if (kk == 0) {
                // refill third stage (overwrites chunk c-1, whose reads all
                // ended before the barrier below of the PREVIOUS iteration)
                int cn = c + 2;
                int st = stage + 2; if (st >= STAGES) st -= STAGES;
                if (cn < CHUNKS) load_chunk(cn, st, sb, Ag, Bg, tid);
                cp_commit();
            }
        }
        // make chunk c+2 resident + publish before next iter's prefetch reads c+1
        // (c+1 already covered; this wait targets the group committed above)
        cp_wait0();
        __syncthreads();
        stage = snext;
    }

    // epilogue: scale (row-wise over N) + bias, fp32 stores
#pragma unroll
    for (int mt = 0; mt < 4; mt++) {
        int r0 = m0 + wm + mt * 16 + (lane >> 2);
        float* o0 = out + (size_t)r0 * NTOT;
        float* o1 = out + (size_t)(r0 + 8) * NTOT;
#pragma unroll
        for (int nt = 0; nt < 4; nt++) {
            int col = n0 + wn + nt * 8 + (lane & 3) * 2;
            float s0 = __ldg(scales + col), s1 = __ldg(scales + col + 1);
            float b0 = __ldg(bias + col),   b1 = __ldg(bias + col + 1);
            float2 v0, v1;
            v0.x = fmaf(acc[mt][nt][0], s0, b0);
            v0.y = fmaf(acc[mt][nt][1], s1, b1);
            v1.x = fmaf(acc[mt][nt][2], s0, b0);
            v1.y = fmaf(acc[mt][nt][3], s1, b1);
            *reinterpret_cast<float2*>(o0 + col) = v0;
            *reinterpret_cast<float2*>(o1 + col) = v1;
        }
    }
}

// ---------------- launch ----------------
extern "C" void kernel_launch(void* const* d_in, const int* in_sizes, int n_in,
                              void* d_out, int out_size) {
    const float* x      = (const float*)d_in[0];
    const int*   q      = (const int*)d_in[1];
    const float* scales = (const float*)d_in[2];
    const float* bias   = (const float*)d_in[3];
    float* out = (float*)d_out;

    prep_kernel<<<NK2 / THREADS, THREADS>>>(q, (const float4*)x);

    cudaFuncSetAttribute(gemm_kernel, cudaFuncAttributeMaxDynamicSharedMemorySize,
                         SMEM_TOTAL);
    gemm_kernel<<<(MTOT / MT) * (NTOT / NT), THREADS, SMEM_TOTAL>>>(scales, bias, out);
}

// round 11
// speedup vs baseline: 1.0750x; 1.0396x over previous
#include <cuda_runtime.h>
#include <cuda_fp16.h>
#include <cstdint>

// ---------------- problem constants ----------------
#define KTOT 4096
#define NTOT 11008
#define MTOT 8192

#define MT 128
#define NT 64
#define BK 64
#define STAGES 3
#define THREADS 256
#define CHUNKS (KTOT / BK)          // 64

#define A_BYTES (MT * BK * 2)       // 16384
#define B_BYTES (NT * BK * 2)       // 8192
#define STAGE_BYTES (A_BYTES + B_BYTES)   // 24576
#define SMEM_TOTAL (STAGES * STAGE_BYTES) // 73728 -> 3 CTAs/SM (216KB)

// ---------------- scratch (device globals, no allocs) ----------------
__device__ __align__(16) __half g_Xh[(size_t)MTOT * KTOT];   // 67 MB
__device__ __align__(16) __half g_Wh[(size_t)NTOT * KTOT];   // 90 MB

// ---------------- helpers ----------------
__device__ __forceinline__ uint32_t smem_u32(const void* p) {
    uint32_t a;
    asm("{ .reg .u64 t; cvta.to.shared.u64 t, %1; cvt.u32.u64 %0, t; }"
        : "=r"(a) : "l"(p));
    return a;
}
// 128-byte rows (64 fp16), 8 16B groups/row, XOR by (row&7):
// conflict-free for ldmatrix 8-row phases AND cp.async writes.
__device__ __forceinline__ uint32_t swz(int row, int g) {
    return (uint32_t)((row << 7) + (((g ^ (row & 7)) & 7) << 4));
}
__device__ __forceinline__ void cp16(uint32_t dst, const void* src) {
    asm volatile("cp.async.cg.shared.global [%0], [%1], 16;"
                 :: "r"(dst), "l"(src) : "memory");
}
__device__ __forceinline__ void cp_commit() {
    asm volatile("cp.async.commit_group;" ::: "memory");
}
__device__ __forceinline__ void cp_wait1() {
    asm volatile("cp.async.wait_group 1;" ::: "memory");
}
__device__ __forceinline__ void ldsm4(uint32_t* r, uint32_t addr) {
    asm volatile("ldmatrix.sync.aligned.m8n8.x4.shared.b16 {%0,%1,%2,%3}, [%4];"
                 : "=r"(r[0]), "=r"(r[1]), "=r"(r[2]), "=r"(r[3]) : "r"(addr));
}
__device__ __forceinline__ void mma16816(float* c, const uint32_t* a,
                                         uint32_t b0, uint32_t b1) {
    asm volatile(
        "mma.sync.aligned.m16n8k16.row.col.f32.f16.f16.f32 "
        "{%0,%1,%2,%3}, {%4,%5,%6,%7}, {%8,%9}, {%0,%1,%2,%3};"
        : "+f"(c[0]), "+f"(c[1]), "+f"(c[2]), "+f"(c[3])
        : "r"(a[0]), "r"(a[1]), "r"(a[2]), "r"(a[3]), "r"(b0), "r"(b1));
}

// ---------------- fused prep kernel ----------------
#define NK2 (NTOT * (KTOT / 2))          // 22,544,384
#define MK4 ((MTOT / 4) * KTOT)          // 8,388,608
__global__ void prep_kernel(const int* __restrict__ q, const float4* __restrict__ x) {
    size_t i = (size_t)blockIdx.x * THREADS + threadIdx.x;
    int v = q[i];
    int lo = (((v & 15) + 8) & 15) - 8;
    int hi = ((((v >> 4) & 15) + 8) & 15) - 8;
    __half2 w;
    w.x = __int2half_rn(lo);
    w.y = __int2half_rn(hi);
    reinterpret_cast<__half2*>(g_Wh)[i] = w;
    if (i < (size_t)MK4) {
        float4 xv = x[i];
        __half2* o = reinterpret_cast<__half2*>(g_Xh);
        o[2 * i]     = __floats2half2_rn(xv.x, xv.y);
        o[2 * i + 1] = __floats2half2_rn(xv.z, xv.w);
    }
}

// ---------------- GEMM ----------------
__device__ __forceinline__ void load_chunk(int c, int stage, uint32_t sb,
                                           const __half* Ag, const __half* Bg,
                                           int tid) {
    uint32_t s_a = sb + stage * STAGE_BYTES;
    uint32_t s_b = s_a + A_BYTES;
    const char* a = reinterpret_cast<const char*>(Ag) + (size_t)c * BK * 2;
    const char* b = reinterpret_cast<const char*>(Bg) + (size_t)c * BK * 2;
    const size_t rowb = (size_t)KTOT * 2;
#pragma unroll
    for (int i = 0; i < 4; i++) {            // A: 128 rows x 8 vecs
        int v = tid + i * THREADS;
        int row = v >> 3, g = v & 7;
        cp16(s_a + swz(row, g), a + (size_t)row * rowb + g * 16);
    }
#pragma unroll
    for (int i = 0; i < 2; i++) {            // B: 64 rows x 8 vecs
        int v = tid + i * THREADS;
        int row = v >> 3, g = v & 7;
        cp16(s_b + swz(row, g), b + (size_t)row * rowb + g * 16);
    }
}

__global__ void __launch_bounds__(THREADS, 3)
gemm_kernel(const float* __restrict__ scales, const float* __restrict__ bias,
            float* __restrict__ out) {
    extern __shared__ char smem[];
    uint32_t sb = smem_u32(smem);
    int tid = threadIdx.x, lane = tid & 31, wid = tid >> 5;

    // grouped rasterization (8 m-tiles per group) for L2 reuse of the W panel
    const int NTILES = NTOT / NT;   // 172
    const int GROUP = 8;
    int pid = blockIdx.x;
    int gsz = GROUP * NTILES;
    int g = pid / gsz, r = pid % gsz;
    int mtile = g * GROUP + (r % GROUP);
    int ntile = r / GROUP;
    int m0 = mtile * MT, n0 = ntile * NT;

    const __half* Ag = g_Xh + (size_t)m0 * KTOT;
    const __half* Bg = g_Wh + (size_t)n0 * KTOT;

    // warp grid: 4 (m) x 2 (n); warp tile 32x32
    const int wm = (wid >> 1) * 32;
    const int wn = (wid & 1) * 32;

    float acc[2][4][4];
#pragma unroll
    for (int i = 0; i < 2; i++)
#pragma unroll
        for (int j = 0; j < 4; j++)
#pragma unroll
            for (int l = 0; l < 4; l++) acc[i][j][l] = 0.0f;

    // prologue: 2 stages in flight
#pragma unroll
    for (int s = 0; s < STAGES - 1; s++) {
        load_chunk(s, s, sb, Ag, Bg, tid);
        cp_commit();
    }

    int stage = 0;
    for (int c = 0; c < CHUNKS; c++) {
        cp_wait1();              // stage for chunk c resident
        __syncthreads();
        {
            int cn = c + STAGES - 1;
            if (cn < CHUNKS) {
                int st = stage + 2; if (st >= STAGES) st -= STAGES;
                load_chunk(cn, st, sb, Ag, Bg, tid);
            }
            cp_commit();         // keep group count fixed at tail
        }

        uint32_t sa = sb + stage * STAGE_BYTES;
        uint32_t sB = sa + A_BYTES;
#pragma unroll
        for (int kk = 0; kk < 4; kk++) {     // 4 k16 steps per BK=64 chunk
            int gg = kk * 2 + (lane >> 4);
            uint32_t af[2][4], bf[2][4];
#pragma unroll
            for (int mt = 0; mt < 2; mt++) {
                int row = wm + mt * 16 + (lane & 15);
                ldsm4(af[mt], sa + swz(row, gg));
            }
#pragma unroll
            for (int np = 0; np < 2; np++) {
                int row = wn + np * 16 + (lane & 15);
                ldsm4(bf[np], sB + swz(row, gg));
            }
#pragma unroll
            for (int mt = 0; mt < 2; mt++)
#pragma unroll
                for (int nt = 0; nt < 4; nt++)
                    mma16816(acc[mt][nt], af[mt],
                             bf[nt >> 1][nt & 1],
                             bf[nt >> 1][(nt & 1) + 2]);
        }
        stage++; if (stage >= STAGES) stage = 0;
    }

    // epilogue: scale (row-wise over N) + bias, fp32 stores
#pragma unroll
    for (int mt = 0; mt < 2; mt++) {
        int r0 = m0 + wm + mt * 16 + (lane >> 2);
        float* o0 = out + (size_t)r0 * NTOT;
        float* o1 = out + (size_t)(r0 + 8) * NTOT;
#pragma unroll
        for (int nt = 0; nt < 4; nt++) {
            int col = n0 + wn + nt * 8 + (lane & 3) * 2;
            float s0 = __ldg(scales + col), s1 = __ldg(scales + col + 1);
            float b0 = __ldg(bias + col),   b1 = __ldg(bias + col + 1);
            float2 v0, v1;
            v0.x = fmaf(acc[mt][nt][0], s0, b0);
            v0.y = fmaf(acc[mt][nt][1], s1, b1);
            v1.x = fmaf(acc[mt][nt][2], s0, b0);
            v1.y = fmaf(acc[mt][nt][3], s1, b1);
            *reinterpret_cast<float2*>(o0 + col) = v0;
            *reinterpret_cast<float2*>(o1 + col) = v1;
        }
    }
}

// ---------------- launch ----------------
extern "C" void kernel_launch(void* const* d_in, const int* in_sizes, int n_in,
                              void* d_out, int out_size) {
    const float* x      = (const float*)d_in[0];
    const int*   q      = (const int*)d_in[1];
    const float* scales = (const float*)d_in[2];
    const float* bias   = (const float*)d_in[3];
    float* out = (float*)d_out;

    prep_kernel<<<NK2 / THREADS, THREADS>>>(q, (const float4*)x);

    cudaFuncSetAttribute(gemm_kernel, cudaFuncAttributeMaxDynamicSharedMemorySize,
                         SMEM_TOTAL);
    gemm_kernel<<<(MTOT / MT) * (NTOT / NT), THREADS, SMEM_TOTAL>>>(scales, bias, out);
}

// round 12
// speedup vs baseline: 1.1079x; 1.0306x over previous
#include <cuda_runtime.h>
#include <cuda_fp16.h>
#include <cstdint>

// ---------------- problem constants ----------------
#define KTOT 4096
#define NTOT 11008
#define MTOT 8192

#define MT 128
#define NT 128
#define BK 64
#define STAGES 3
#define THREADS 256
#define CHUNKS (KTOT / BK)          // 64

#define A_BYTES (MT * BK * 2)       // 16384
#define B_BYTES (NT * BK * 2)       // 16384
#define STAGE_BYTES (A_BYTES + B_BYTES)   // 32768
#define SMEM_TOTAL (STAGES * STAGE_BYTES) // 98304 (96KB) -> 2 CTAs/SM

// ---------------- scratch (device globals, no allocs) ----------------
__device__ __align__(16) __half g_Xh[(size_t)MTOT * KTOT];   // 67 MB
__device__ __align__(16) __half g_Wh[(size_t)NTOT * KTOT];   // 90 MB

// ---------------- helpers ----------------
__device__ __forceinline__ uint32_t smem_u32(const void* p) {
    uint32_t a;
    asm("{ .reg .u64 t; cvta.to.shared.u64 t, %1; cvt.u32.u64 %0, t; }"
        : "=r"(a) : "l"(p));
    return a;
}
// 128-byte rows (64 fp16), 8 16B groups/row, XOR by (row&7):
// conflict-free for ldmatrix 8-row phases AND cp.async writes.
__device__ __forceinline__ uint32_t swz(int row, int g) {
    return (uint32_t)((row << 7) + (((g ^ (row & 7)) & 7) << 4));
}
__device__ __forceinline__ void cp16(uint32_t dst, const void* src) {
    asm volatile("cp.async.cg.shared.global [%0], [%1], 16;"
                 :: "r"(dst), "l"(src) : "memory");
}
__device__ __forceinline__ void cp_commit() {
    asm volatile("cp.async.commit_group;" ::: "memory");
}
__device__ __forceinline__ void cp_wait1() {
    asm volatile("cp.async.wait_group 1;" ::: "memory");
}
__device__ __forceinline__ void ldsm4(uint32_t* r, uint32_t addr) {
    asm volatile("ldmatrix.sync.aligned.m8n8.x4.shared.b16 {%0,%1,%2,%3}, [%4];"
                 : "=r"(r[0]), "=r"(r[1]), "=r"(r[2]), "=r"(r[3]) : "r"(addr));
}
__device__ __forceinline__ void mma16816(float* c, const uint32_t* a,
                                         uint32_t b0, uint32_t b1) {
    asm volatile(
        "mma.sync.aligned.m16n8k16.row.col.f32.f16.f16.f32 "
        "{%0,%1,%2,%3}, {%4,%5,%6,%7}, {%8,%9}, {%0,%1,%2,%3};"
        : "+f"(c[0]), "+f"(c[1]), "+f"(c[2]), "+f"(c[3])
        : "r"(a[0]), "r"(a[1]), "r"(a[2]), "r"(a[3]), "r"(b0), "r"(b1));
}

// ---------------- fused prep kernel ----------------
#define NK2 (NTOT * (KTOT / 2))          // 22,544,384
#define MK4 ((MTOT / 4) * KTOT)          // 8,388,608
__global__ void prep_kernel(const int* __restrict__ q, const float4* __restrict__ x) {
    size_t i = (size_t)blockIdx.x * THREADS + threadIdx.x;
    int v = q[i];
    int lo = (((v & 15) + 8) & 15) - 8;
    int hi = ((((v >> 4) & 15) + 8) & 15) - 8;
    __half2 w;
    w.x = __int2half_rn(lo);
    w.y = __int2half_rn(hi);
    reinterpret_cast<__half2*>(g_Wh)[i] = w;
    if (i < (size_t)MK4) {
        float4 xv = x[i];
        __half2* o = reinterpret_cast<__half2*>(g_Xh);
        o[2 * i]     = __floats2half2_rn(xv.x, xv.y);
        o[2 * i + 1] = __floats2half2_rn(xv.z, xv.w);
    }
}

// ---------------- GEMM ----------------
__device__ __forceinline__ void load_chunk(int c, int stage, uint32_t sb,
                                           const __half* Ag, const __half* Bg,
                                           int tid) {
    uint32_t s_a = sb + stage * STAGE_BYTES;
    uint32_t s_b = s_a + A_BYTES;
    const char* a = reinterpret_cast<const char*>(Ag) + (size_t)c * BK * 2;
    const char* b = reinterpret_cast<const char*>(Bg) + (size_t)c * BK * 2;
    const size_t rowb = (size_t)KTOT * 2;
#pragma unroll
    for (int i = 0; i < 4; i++) {            // A: 128 rows x 8 vecs
        int v = tid + i * THREADS;
        int row = v >> 3, g = v & 7;
        cp16(s_a + swz(row, g), a + (size_t)row * rowb + g * 16);
    }
#pragma unroll
    for (int i = 0; i < 4; i++) {            // B: 128 rows x 8 vecs
        int v = tid + i * THREADS;
        int row = v >> 3, g = v & 7;
        cp16(s_b + swz(row, g), b + (size_t)row * rowb + g * 16);
    }
}

__device__ __forceinline__ void load_frags(uint32_t sa, uint32_t sB, int kk,
                                           int wm, int wn, int lane,
                                           uint32_t af[4][4], uint32_t bf[2][4]) {
    int gg = kk * 2 + (lane >> 4);
#pragma unroll
    for (int mt = 0; mt < 4; mt++) {
        int row = wm + mt * 16 + (lane & 15);
        ldsm4(af[mt], sa + swz(row, gg));
    }
#pragma unroll
    for (int np = 0; np < 2; np++) {
        int row = wn + np * 16 + (lane & 15);
        ldsm4(bf[np], sB + swz(row, gg));
    }
}

__global__ void __launch_bounds__(THREADS, 2)
gemm_kernel(const float* __restrict__ scales, const float* __restrict__ bias,
            float* __restrict__ out) {
    extern __shared__ char smem[];
    uint32_t sb = smem_u32(smem);
    int tid = threadIdx.x, lane = tid & 31, wid = tid >> 5;

    // grouped rasterization (8 m-tiles per group) for L2 reuse of the W panel
    const int NTILES = NTOT / NT;   // 86
    const int GROUP = 8;
    int pid = blockIdx.x;
    int gsz = GROUP * NTILES;
    int g = pid / gsz, r = pid % gsz;
    int mtile = g * GROUP + (r % GROUP);
    int ntile = r / GROUP;
    int m0 = mtile * MT, n0 = ntile * NT;

    const __half* Ag = g_Xh + (size_t)m0 * KTOT;
    const __half* Bg = g_Wh + (size_t)n0 * KTOT;

    // warp grid: 2 (m) x 4 (n); warp tile 64x32
    const int wm = (wid >> 2) * 64;
    const int wn = (wid & 3) * 32;
    const int koff = wid & 3;    // per-warp k-step rotation (de-phasing)

    float acc[4][4][4];
#pragma unroll
    for (int i = 0; i < 4; i++)
#pragma unroll
        for (int j = 0; j < 4; j++)
#pragma unroll
            for (int l = 0; l < 4; l++) acc[i][j][l] = 0.0f;

    // prologue: 2 stages in flight
#pragma unroll
    for (int s = 0; s < STAGES - 1; s++) {
        load_chunk(s, s, sb, Ag, Bg, tid);
        cp_commit();
    }

    uint32_t af[2][4][4], bf[2][2][4];
    int stage = 0;
    for (int c = 0; c < CHUNKS; c++) {
        cp_wait1();              // stage for chunk c resident
        __syncthreads();         // all warps done reading stage being refilled

        uint32_t sa = sb + stage * STAGE_BYTES;
        uint32_t sB = sa + A_BYTES;
        // first k-step for THIS warp is rotated by koff
        load_frags(sa, sB, koff, wm, wn, lane, af[0], bf[0]);
#pragma unroll
        for (int j = 0; j < 4; j++) {        // 4 k16 steps, rotated order
            int cur = j & 1;
            if (j < 3) {
                int kk = koff + j + 1; kk &= 3;
                load_frags(sa, sB, kk, wm, wn, lane, af[cur ^ 1], bf[cur ^ 1]);
            }
#pragma unroll
            for (int mt = 0; mt < 4; mt++)
#pragma unroll
                for (int nt = 0; nt < 4; nt++)
                    mma16816(acc[mt][nt], af[cur][mt],
                             bf[cur][nt >> 1][nt & 1],
                             bf[cur][nt >> 1][(nt & 1) + 2]);
            if (j == 0) {
                // deferred gmem refill: off the barrier->HMMA critical path
                int cn = c + STAGES - 1;
                if (cn < CHUNKS) {
                    int st = stage + 2; if (st >= STAGES) st -= STAGES;
                    load_chunk(cn, st, sb, Ag, Bg, tid);
                }
                cp_commit();     // keep group count fixed at tail
            }
        }
        stage++; if (stage >= STAGES) stage = 0;
    }

    // epilogue: scale (row-wise over N) + bias, fp32 stores
#pragma unroll
    for (int mt = 0; mt < 4; mt++) {
        int r0 = m0 + wm + mt * 16 + (lane >> 2);
        float* o0 = out + (size_t)r0 * NTOT;
        float* o1 = out + (size_t)(r0 + 8) * NTOT;
#pragma unroll
        for (int nt = 0; nt < 4; nt++) {
            int col = n0 + wn + nt * 8 + (lane & 3) * 2;
            float s0 = __ldg(scales + col), s1 = __ldg(scales + col + 1);
            float b0 = __ldg(bias + col),   b1 = __ldg(bias + col + 1);
            float2 v0, v1;
            v0.x = fmaf(acc[mt][nt][0], s0, b0);
            v0.y = fmaf(acc[mt][nt][1], s1, b1);
            v1.x = fmaf(acc[mt][nt][2], s0, b0);
            v1.y = fmaf(acc[mt][nt][3], s1, b1);
            *reinterpret_cast<float2*>(o0 + col) = v0;
            *reinterpret_cast<float2*>(o1 + col) = v1;
        }
    }
}

// ---------------- launch ----------------
extern "C" void kernel_launch(void* const* d_in, const int* in_sizes, int n_in,
                              void* d_out, int out_size) {
    const float* x      = (const float*)d_in[0];
    const int*   q      = (const int*)d_in[1];
    const float* scales = (const float*)d_in[2];
    const float* bias   = (const float*)d_in[3];
    float* out = (float*)d_out;

    prep_kernel<<<NK2 / THREADS, THREADS>>>(q, (const float4*)x);

    cudaFuncSetAttribute(gemm_kernel, cudaFuncAttributeMaxDynamicSharedMemorySize,
                         SMEM_TOTAL);
    gemm_kernel<<<(MTOT / MT) * (NTOT / NT), THREADS, SMEM_TOTAL>>>(scales, bias, out);
}